// round 14
// baseline (speedup 1.0000x reference)
#include <cuda_runtime.h>
#include <cuda_bf16.h>
#include <cstdint>

#define LSEQ 4096
#define DIN  512
#define NH   8
#define NB   2

typedef unsigned short ushort_t;
static const size_t bS = 512 * 512;
static const size_t bX = (size_t)LSEQ * DIN;   // 2,097,152

// ---------------- device scratch ----------------
__device__ __align__(256) ushort_t g_xh [NB * LSEQ * DIN];
__device__ __align__(256) ushort_t g_xl [NB * LSEQ * DIN];
__device__ __align__(256) ushort_t g_xTh[NB * DIN * LSEQ];
__device__ __align__(256) ushort_t g_xTl[NB * DIN * LSEQ];
__device__ __align__(256) float    g_Gp [NB * 4 * 512 * 512];
__device__ __align__(256) float    g_Op [NB * 2 * LSEQ * DIN];   // out split-K partials
__device__ __align__(256) ushort_t g_Gh [NB * 512 * 512];
__device__ __align__(256) ushort_t g_Gl [NB * 512 * 512];
__device__ __align__(256) ushort_t g_PTh[NB * 512 * 512];
__device__ __align__(256) ushort_t g_PTl[NB * 512 * 512];
__device__ __align__(256) ushort_t g_RTh[NB * NH * 64 * 64];
__device__ __align__(256) ushort_t g_RTl[NB * NH * 64 * 64];
__device__ __align__(256) ushort_t g_Uh [NB * 512 * 512];
__device__ __align__(256) ushort_t g_Ul [NB * 512 * 512];
__device__ __align__(256) ushort_t g_CTh[NB * 512 * 512];
__device__ __align__(256) ushort_t g_CTl[NB * 512 * 512];
__device__ __align__(256) ushort_t g_Wkbh[512 * 512];     // [c=h*64+k][m]
__device__ __align__(256) ushort_t g_Wkbl[512 * 512];
__device__ __align__(256) ushort_t g_Wobh[512 * 512];     // [o][hv]
__device__ __align__(256) ushort_t g_Wobl[512 * 512];
__device__ __align__(256) ushort_t g_WvTh[512 * 512];     // [hv][n]
__device__ __align__(256) ushort_t g_WvTl[512 * 512];
__device__ __align__(256) ushort_t g_Wqbh[NH * 512 * 64]; // [h*512+j][k]
__device__ __align__(256) ushort_t g_Wqbl[NH * 512 * 64];

// ---------------- helpers ----------------
#define SWZ(o) ((o) ^ (((o) >> 3) & 0x70))

__device__ __forceinline__ uint32_t smem_u32(const void* p) {
    uint32_t a;
    asm("{ .reg .u64 t; cvta.to.shared.u64 t, %1; cvt.u32.u64 %0, t; }" : "=r"(a) : "l"(p));
    return a;
}
__device__ __forceinline__ ushort_t f2bf(float v) {
    __nv_bfloat16 b = __float2bfloat16(v);
    return *reinterpret_cast<ushort_t*>(&b);
}
__device__ __forceinline__ float bfhi(ushort_t h) {
    return __uint_as_float(((uint32_t)h) << 16);
}
__device__ __forceinline__ void ldsm4(uint32_t* f, uint32_t addr) {
    asm volatile("ldmatrix.sync.aligned.m8n8.x4.shared.b16 {%0,%1,%2,%3}, [%4];"
                 : "=r"(f[0]), "=r"(f[1]), "=r"(f[2]), "=r"(f[3]) : "r"(addr));
}
__device__ __forceinline__ void mma16816(float* d, const uint32_t* a, const uint32_t* b) {
    asm volatile("mma.sync.aligned.m16n8k16.row.col.f32.bf16.bf16.f32 "
                 "{%0,%1,%2,%3}, {%4,%5,%6,%7}, {%8,%9}, {%0,%1,%2,%3};"
                 : "+f"(d[0]), "+f"(d[1]), "+f"(d[2]), "+f"(d[3])
                 : "r"(a[0]), "r"(a[1]), "r"(a[2]), "r"(a[3]), "r"(b[0]), "r"(b[1]));
}
__device__ __forceinline__ void cpa16(uint32_t s, const void* g) {
    asm volatile("cp.async.cg.shared.global [%0], [%1], 16;" :: "r"(s), "l"(g) : "memory");
}
#define CP_COMMIT() asm volatile("cp.async.commit_group;" ::: "memory")
template <int N>
__device__ __forceinline__ void cp_wait() {
    asm volatile("cp.async.wait_group %0;" :: "n"(N) : "memory");
}

// ===========================================================================
// Generic bf16x3 GEMM via mma.sync (HMMA): C(m,n) = sum_k A(m,k)*B(n,k).
// A, B pre-split bf16 hi/lo, K contiguous. 256 threads, warp grid 2(m)x4(n).
// KB: K-tile depth (32 or 64). Multi-stage cp.async pipeline (4 or 3 stages).
// Persistent 1D grid over ntot tiles; decode xo/yo/z, z = b*nsl + sl.
// EPI 0: fp32 row-major out. EPI 1: bf16 hi/lo row-major out.
// ===========================================================================
template <int BM, int BN, int EPI, int KB>
__global__ void __launch_bounds__(256, 1)
gemm_bf3(const ushort_t* __restrict__ Ah, const ushort_t* __restrict__ Al,
         const ushort_t* __restrict__ Bh, const ushort_t* __restrict__ Bl,
         float* __restrict__ Cf, ushort_t* __restrict__ Ch, ushort_t* __restrict__ Cl,
         int K, int lda, int ldb, int ldc,
         long bA, long slA, long bB, long slB, long bC, long slC, int nsl,
         int ntx, int nty, int ntot) {
    constexpr int WM = BM / 2, WN = BN / 4;
    constexpr int MT = WM / 16, NT = WN / 8, PB = WN / 16;
    constexpr int SEGS = KB / 8;                 // 16B segments per row
    constexpr int SSH  = (KB == 64) ? 3 : 2;     // shift for c -> (r, sg)
    constexpr int KS   = KB / 16;                // k-subiters per ktile
    constexpr int AB   = BM * KB * 2;            // bytes per A array
    constexpr int BB   = BN * KB * 2;
    constexpr int SS   = 2 * AB + 2 * BB;        // stage bytes
    constexpr int NSTG = (4 * SS <= 196608) ? 4 : 3;

    extern __shared__ char dsm[];
    uint32_t sb = smem_u32(dsm);
    int tid = threadIdx.x, lane = tid & 31, wid = tid >> 5;
    int wm = wid & 1, wn = wid >> 1;
    const int nkt = K / KB;

    auto rowoff = [](int r) -> uint32_t {
        return (KB == 32) ? (uint32_t)((r >> 1) * 128 + (r & 1) * 64)
                          : (uint32_t)(r * 128);
    };

#pragma unroll 1
    for (int t = blockIdx.x; t < ntot; t += gridDim.x) {
        int xo = t % ntx;
        int rest = t / ntx;
        int yo = rest % nty;
        int z = rest / nty;
        int b = z / nsl, sl = z - b * nsl;
        int m0 = yo * BM, n0 = xo * BN;
        const ushort_t* pAh = Ah + b * bA + sl * slA + (size_t)m0 * lda;
        const ushort_t* pAl = Al + b * bA + sl * slA + (size_t)m0 * lda;
        const ushort_t* pBh = Bh + b * bB + sl * slB + (size_t)n0 * ldb;
        const ushort_t* pBl = Bl + b * bB + sl * slB + (size_t)n0 * ldb;

        float acc[MT][NT][4];
#pragma unroll
        for (int i = 0; i < MT; i++)
#pragma unroll
            for (int j = 0; j < NT; j++)
#pragma unroll
                for (int q = 0; q < 4; q++) acc[i][j][q] = 0.f;

        auto load_stage = [&](int stg, int kt, bool pred) {
            if (pred) {
                uint32_t s0 = sb + stg * SS;
                int ke = kt * KB;
#pragma unroll
                for (int c = tid; c < BM * SEGS; c += 256) {
                    int r = c >> SSH, sg = c & (SEGS - 1);
                    uint32_t o = SWZ(rowoff(r) + sg * 16);
                    cpa16(s0 + o,      pAh + (size_t)r * lda + ke + sg * 8);
                    cpa16(s0 + AB + o, pAl + (size_t)r * lda + ke + sg * 8);
                }
#pragma unroll
                for (int c = tid; c < BN * SEGS; c += 256) {
                    int r = c >> SSH, sg = c & (SEGS - 1);
                    uint32_t o = SWZ(rowoff(r) + sg * 16);
                    cpa16(s0 + 2 * AB + o,      pBh + (size_t)r * ldb + ke + sg * 8);
                    cpa16(s0 + 2 * AB + BB + o, pBl + (size_t)r * ldb + ke + sg * 8);
                }
            }
            CP_COMMIT();
        };

#pragma unroll
        for (int s = 0; s < NSTG - 1; s++) load_stage(s, s, s < nkt);

#pragma unroll 1
        for (int kt = 0; kt < nkt; kt++) {
            cp_wait<NSTG - 2>();
            __syncthreads();
            load_stage((kt + NSTG - 1) % NSTG, kt + NSTG - 1, kt + NSTG - 1 < nkt);

            uint32_t stb = sb + (kt % NSTG) * SS;
#pragma unroll
            for (int ks = 0; ks < KS; ks++) {
                uint32_t ah[MT][4], al[MT][4], bh[PB][4], bl[PB][4];
                int ar  = wm * WM + (lane & 15);
                int akk = ks * 16 + (lane >> 4) * 8;
#pragma unroll
                for (int mt = 0; mt < MT; mt++) {
                    int r = ar + mt * 16;
                    uint32_t o = SWZ(rowoff(r) + akk * 2);
                    ldsm4(ah[mt], stb + o);
                    ldsm4(al[mt], stb + AB + o);
                }
                int bn  = wn * WN + (lane & 7) + ((lane >> 4) & 1) * 8;
                int bkk = ks * 16 + ((lane >> 3) & 1) * 8;
#pragma unroll
                for (int p = 0; p < PB; p++) {
                    int r = bn + p * 16;
                    uint32_t o = SWZ(rowoff(r) + bkk * 2);
                    ldsm4(bh[p], stb + 2 * AB + o);
                    ldsm4(bl[p], stb + 2 * AB + BB + o);
                }
#pragma unroll
                for (int mt = 0; mt < MT; mt++)
#pragma unroll
                    for (int nt = 0; nt < NT; nt++) {
                        const uint32_t* fh = &bh[nt >> 1][(nt & 1) * 2];
                        const uint32_t* fl = &bl[nt >> 1][(nt & 1) * 2];
                        mma16816(acc[mt][nt], ah[mt], fh);
                        mma16816(acc[mt][nt], al[mt], fh);
                        mma16816(acc[mt][nt], ah[mt], fl);
                    }
            }
        }

        long offC = b * bC + sl * slC;
        int r0 = m0 + wm * WM + (lane >> 2);
        int c0 = n0 + wn * WN + (lane & 3) * 2;
        if (EPI == 0) {
            float* Co = Cf + offC;
#pragma unroll
            for (int mt = 0; mt < MT; mt++)
#pragma unroll
                for (int nt = 0; nt < NT; nt++) {
                    int r = r0 + mt * 16, c = c0 + nt * 8;
                    *(float2*)&Co[(size_t)r * ldc + c] =
                        make_float2(acc[mt][nt][0], acc[mt][nt][1]);
                    *(float2*)&Co[(size_t)(r + 8) * ldc + c] =
                        make_float2(acc[mt][nt][2], acc[mt][nt][3]);
                }
        } else {
            ushort_t* Hh = Ch + offC;
            ushort_t* Hl = Cl + offC;
#pragma unroll
            for (int mt = 0; mt < MT; mt++)
#pragma unroll
                for (int nt = 0; nt < NT; nt++)
#pragma unroll
                    for (int hf = 0; hf < 2; hf++) {
                        int r = r0 + mt * 16 + hf * 8, c = c0 + nt * 8;
                        float v0 = acc[mt][nt][hf * 2], v1 = acc[mt][nt][hf * 2 + 1];
                        ushort_t h0 = f2bf(v0), h1 = f2bf(v1);
                        *(ushort2*)&Hh[(size_t)r * ldc + c] = make_ushort2(h0, h1);
                        *(ushort2*)&Hl[(size_t)r * ldc + c] =
                            make_ushort2(f2bf(v0 - bfhi(h0)), f2bf(v1 - bfhi(h1)));
                    }
        }
        __syncthreads();   // protect smem: next tile's prologue may reuse any slot
    }
}

// ===========================================================================
// Fused input pack (x read once: transpose blocks also emit row-major split)
// ===========================================================================
__global__ void pack_all(const float* __restrict__ x, const float* __restrict__ Wq,
                         const float* __restrict__ Wk, const float* __restrict__ Wv,
                         const float* __restrict__ Wo) {
    __shared__ float s[32][33];
    int blk = blockIdx.x, tid = threadIdx.x;
    if (blk < 4096) {                      // x: transpose + row-major split
        int bx = blk & 127, by = (blk >> 7) & 15, b = blk >> 11;
        int r0 = bx * 32, c0 = by * 32;
        int tx = tid & 31, ty = tid >> 5;
        const float* xb = x + (size_t)b * bX;
#pragma unroll
        for (int q = 0; q < 4; q++) {
            int r = r0 + ty + 8 * q;
            float v = xb[(size_t)r * DIN + c0 + tx];
            s[ty + 8 * q][tx] = v;
            ushort_t h = f2bf(v);
            size_t o = (size_t)b * bX + (size_t)r * DIN + c0 + tx;
            g_xh[o] = h;
            g_xl[o] = f2bf(v - bfhi(h));
        }
        __syncthreads();
#pragma unroll
        for (int q = 0; q < 4; q++) {
            int cd = ty + 8 * q;
            float v = s[tx][cd];
            ushort_t h = f2bf(v);
            size_t o = ((size_t)b * DIN + c0 + cd) * LSEQ + r0 + tx;
            g_xTh[o] = h;
            g_xTl[o] = f2bf(v - bfhi(h));
        }
    } else if (blk < 5120) {               // Wkb[c][m] = Wk[h][m][k]
        int i = (blk - 4096) * 256 + tid;
        int c = i >> 9, m = i & 511, h = c >> 6, kd = c & 63;
        float v = Wk[h * 32768 + m * 64 + kd];
        ushort_t hh = f2bf(v);
        g_Wkbh[i] = hh; g_Wkbl[i] = f2bf(v - bfhi(hh));
    } else if (blk < 6144) {               // Wob[o][hv] = Wo[hv][o]
        int i = (blk - 5120) * 256 + tid;
        int o = i >> 9, hv = i & 511;
        float v = Wo[hv * 512 + o];
        ushort_t hh = f2bf(v);
        g_Wobh[i] = hh; g_Wobl[i] = f2bf(v - bfhi(hh));
    } else if (blk < 7168) {               // WvT[hv][n] = Wv[h][n][v]
        int i = (blk - 6144) * 256 + tid;
        int row = i >> 9, n = i & 511, h = row >> 6, vv = row & 63;
        float v = Wv[h * 32768 + n * 64 + vv];
        ushort_t hh = f2bf(v);
        g_WvTh[i] = hh; g_WvTl[i] = f2bf(v - bfhi(hh));
    } else {                               // Wqb straight split
        int i = (blk - 7168) * 256 + tid;
        float v = Wq[i];
        ushort_t hh = f2bf(v);
        g_Wqbh[i] = hh; g_Wqbl[i] = f2bf(v - bfhi(hh));
    }
}

// ===========================================================================
// reduce_4: sum 4 fp32 partials per batch -> bf16 hi/lo (for G)
// ===========================================================================
__global__ void reduce_4(const float* __restrict__ src,
                         ushort_t* __restrict__ oh, ushort_t* __restrict__ ol) {
    int i = blockIdx.x * 256 + threadIdx.x;          // over NB*65536 float4
    int b = i >> 16, e = i & 65535;
    const float4* p = (const float4*)src;
    float4 v = p[(size_t)(b * 4) * 65536 + e];
#pragma unroll
    for (int q = 1; q < 4; q++) {
        float4 t = p[(size_t)(b * 4 + q) * 65536 + e];
        v.x += t.x; v.y += t.y; v.z += t.z; v.w += t.w;
    }
    ushort_t h0 = f2bf(v.x), h1 = f2bf(v.y), h2 = f2bf(v.z), h3 = f2bf(v.w);
    size_t o = (size_t)b * 65536 + e;
    ((ushort4*)oh)[o] = make_ushort4(h0, h1, h2, h3);
    ((ushort4*)ol)[o] = make_ushort4(f2bf(v.x - bfhi(h0)), f2bf(v.y - bfhi(h1)),
                                     f2bf(v.z - bfhi(h2)), f2bf(v.w - bfhi(h3)));
}

// ===========================================================================
// reduce_out: out[b] = Op[b,0] + Op[b,1]  (fp32)
// ===========================================================================
__global__ void reduce_out(const float* __restrict__ src, float* __restrict__ dst) {
    int i = blockIdx.x * 256 + threadIdx.x;      // over NB * (bX/4) = 1,048,576
    int b = i >> 19, e = i & 524287;
    const float4* p = (const float4*)src;
    float4 a = p[(size_t)(b * 2 + 0) * 524288 + e];
    float4 c = p[(size_t)(b * 2 + 1) * 524288 + e];
    ((float4*)dst)[(size_t)b * 524288 + e] =
        make_float4(a.x + c.x, a.y + c.y, a.z + c.z, a.w + c.w);
}

// ===========================================================================
extern "C" void kernel_launch(void* const* d_in, const int* in_sizes, int n_in,
                              void* d_out, int out_size) {
    const float* x  = (const float*)d_in[0];
    const float* Wq = (const float*)d_in[1];
    const float* Wk = (const float*)d_in[2];
    const float* Wv = (const float*)d_in[3];
    const float* Wo = (const float*)d_in[4];
    float* out = (float*)d_out;

    cudaFuncSetAttribute(gemm_bf3<128,128,0,32>, cudaFuncAttributeMaxDynamicSharedMemorySize, 131072);
    cudaFuncSetAttribute(gemm_bf3<64,64,1,64>,   cudaFuncAttributeMaxDynamicSharedMemorySize, 131072);
    cudaFuncSetAttribute(gemm_bf3<128,64,1,64>,  cudaFuncAttributeMaxDynamicSharedMemorySize, 196608);
    cudaFuncSetAttribute(gemm_bf3<128,128,0,64>, cudaFuncAttributeMaxDynamicSharedMemorySize, 196608);

    ushort_t *xh,*xl,*xTh,*xTl,*Gh,*Gl,*PTh,*PTl,*RTh,*RTl,*Uh,*Ul,*CTh,*CTl;
    ushort_t *Wkbh,*Wkbl,*Wobh,*Wobl,*WvTh,*WvTl,*Wqbh,*Wqbl;
    float *Gp,*Op;
    cudaGetSymbolAddress((void**)&xh,  g_xh);  cudaGetSymbolAddress((void**)&xl,  g_xl);
    cudaGetSymbolAddress((void**)&xTh, g_xTh); cudaGetSymbolAddress((void**)&xTl, g_xTl);
    cudaGetSymbolAddress((void**)&Gh,  g_Gh);  cudaGetSymbolAddress((void**)&Gl,  g_Gl);
    cudaGetSymbolAddress((void**)&PTh, g_PTh); cudaGetSymbolAddress((void**)&PTl, g_PTl);
    cudaGetSymbolAddress((void**)&RTh, g_RTh); cudaGetSymbolAddress((void**)&RTl, g_RTl);
    cudaGetSymbolAddress((void**)&Uh,  g_Uh);  cudaGetSymbolAddress((void**)&Ul,  g_Ul);
    cudaGetSymbolAddress((void**)&CTh, g_CTh); cudaGetSymbolAddress((void**)&CTl, g_CTl);
    cudaGetSymbolAddress((void**)&Wkbh,g_Wkbh);cudaGetSymbolAddress((void**)&Wkbl,g_Wkbl);
    cudaGetSymbolAddress((void**)&Wobh,g_Wobh);cudaGetSymbolAddress((void**)&Wobl,g_Wobl);
    cudaGetSymbolAddress((void**)&WvTh,g_WvTh);cudaGetSymbolAddress((void**)&WvTl,g_WvTl);
    cudaGetSymbolAddress((void**)&Wqbh,g_Wqbh);cudaGetSymbolAddress((void**)&Wqbl,g_Wqbl);
    cudaGetSymbolAddress((void**)&Gp,  g_Gp);  cudaGetSymbolAddress((void**)&Op,  g_Op);

    pack_all<<<8192, 256>>>(x, Wq, Wk, Wv, Wo);

    // G[n][m] = sum_l xT[n][l] xT[m][l]; split-K 4, fp32 partials (128 tiles)
    gemm_bf3<128,128,0,32><<<128, 256, 131072>>>(
        xTh, xTl, xTh, xTl, Gp, nullptr, nullptr,
        1024, LSEQ, LSEQ, 512,
        (long)bX, 1024, (long)bX, 1024, (long)(4*bS), (long)bS, 4,
        4, 4, 128);
    reduce_4<<<512, 256>>>(Gp, Gh, Gl);

    // PT[c][n] = sum_m Wkb[c][m] G[n][m]; 64x64, BK=64, bf16 out (128 tiles)
    gemm_bf3<64,64,1,64><<<128, 256, 131072>>>(
        Wkbh, Wkbl, Gh, Gl, nullptr, PTh, PTl,
        512, 512, 512, 512,
        0, 0, (long)bS, 0, (long)bS, 0, 1,
        8, 8, 128);

    // RT[v][k](b,h) = sum_n WvT[hv][n] PT[hk][n]; batched (b,h) (16 tiles)
    gemm_bf3<64,64,1,64><<<16, 256, 131072>>>(
        WvTh, WvTl, PTh, PTl, nullptr, RTh, RTl,
        512, 512, 512, 64,
        0, 32768, (long)bS, 32768, (long)(NH*4096), 4096, NH,
        1, 1, 16);

    // U[j][hv](b) = sum_k Wqb[hj][k] RT[v][k]; batched (b,h) (64 tiles)
    gemm_bf3<128,64,1,64><<<64, 256, 196608>>>(
        Wqbh, Wqbl, RTh, RTl, nullptr, Uh, Ul,
        64, 64, 64, 512,
        0, 32768, (long)(NH*4096), 4096, (long)bS, 64, NH,
        1, 4, 64);

    // CT[o][j](b) = sum_hv Wob[o][hv] U[j][hv]; 64x64, BK=64 (128 tiles)
    gemm_bf3<64,64,1,64><<<128, 256, 131072>>>(
        Wobh, Wobl, Uh, Ul, nullptr, CTh, CTl,
        512, 512, 512, 512,
        0, 0, (long)bS, 0, (long)bS, 0, 1,
        8, 8, 128);

    // out partials: split-K 2 (K=256 each), BK=64, 512 tiles on 148 CTAs
    gemm_bf3<128,128,0,64><<<148, 256, 196608>>>(
        xh, xl, CTh, CTl, Op, nullptr, nullptr,
        256, 512, 512, 512,
        (long)bX, 256, (long)bS, 256, (long)(2*bX), (long)bX, 2,
        4, 32, 512);
    reduce_out<<<4096, 256>>>(Op, out);
}

// round 15
// speedup vs baseline: 1.2691x; 1.2691x over previous
#include <cuda_runtime.h>
#include <cuda_bf16.h>
#include <cuda_fp16.h>
#include <cstdint>

#define LSEQ 4096
#define DIN  512
#define NH   8
#define NB   2

typedef unsigned short ushort_t;
static const size_t bS = 512 * 512;
static const size_t bX = (size_t)LSEQ * DIN;

// ---------------- device scratch ----------------
__device__ __align__(256) ushort_t g_xh [NB * LSEQ * DIN];   // x fp16 hi (row-major)
__device__ __align__(256) ushort_t g_xl [NB * LSEQ * DIN];   // x fp16 lo
__device__ __align__(256) ushort_t g_xTh[NB * DIN * LSEQ];   // xT fp16 hi
__device__ __align__(256) ushort_t g_xTl[NB * DIN * LSEQ];   // xT fp16 lo
__device__ __align__(256) float    g_Gp [NB * 4 * 512 * 512];
__device__ __align__(256) ushort_t g_Gh [NB * 512 * 512];    // G bf16 hi
__device__ __align__(256) ushort_t g_Gl [NB * 512 * 512];
__device__ __align__(256) ushort_t g_PTh[NB * 512 * 512];
__device__ __align__(256) ushort_t g_PTl[NB * 512 * 512];
__device__ __align__(256) ushort_t g_RTh[NB * NH * 64 * 64];
__device__ __align__(256) ushort_t g_RTl[NB * NH * 64 * 64];
__device__ __align__(256) ushort_t g_Uh [NB * 512 * 512];
__device__ __align__(256) ushort_t g_Ul [NB * 512 * 512];
__device__ __align__(256) ushort_t g_CTh[NB * 512 * 512];    // CT fp16 single, scaled 2^-24
__device__ __align__(256) ushort_t g_Wkbh[512 * 512];
__device__ __align__(256) ushort_t g_Wkbl[512 * 512];
__device__ __align__(256) ushort_t g_Wobh[512 * 512];
__device__ __align__(256) ushort_t g_Wobl[512 * 512];
__device__ __align__(256) ushort_t g_WvTh[512 * 512];
__device__ __align__(256) ushort_t g_WvTl[512 * 512];
__device__ __align__(256) ushort_t g_Wqbh[NH * 512 * 64];
__device__ __align__(256) ushort_t g_Wqbl[NH * 512 * 64];

// ---------------- helpers ----------------
#define SWZ(o) ((o) ^ (((o) >> 3) & 0x70))

__device__ __forceinline__ uint32_t smem_u32(const void* p) {
    uint32_t a;
    asm("{ .reg .u64 t; cvta.to.shared.u64 t, %1; cvt.u32.u64 %0, t; }" : "=r"(a) : "l"(p));
    return a;
}
__device__ __forceinline__ ushort_t f2bf(float v) {
    __nv_bfloat16 b = __float2bfloat16(v);
    return *reinterpret_cast<ushort_t*>(&b);
}
__device__ __forceinline__ float bfhi(ushort_t h) {
    return __uint_as_float(((uint32_t)h) << 16);
}
__device__ __forceinline__ ushort_t f2h(float v) {
    __half h = __float2half_rn(v);
    return *reinterpret_cast<ushort_t*>(&h);
}
__device__ __forceinline__ float h2f(ushort_t u) {
    __half h = *reinterpret_cast<__half*>(&u);
    return __half2float(h);
}
__device__ __forceinline__ void ldsm4(uint32_t* f, uint32_t addr) {
    asm volatile("ldmatrix.sync.aligned.m8n8.x4.shared.b16 {%0,%1,%2,%3}, [%4];"
                 : "=r"(f[0]), "=r"(f[1]), "=r"(f[2]), "=r"(f[3]) : "r"(addr));
}
__device__ __forceinline__ void mma_bf16(float* d, const uint32_t* a, const uint32_t* b) {
    asm volatile("mma.sync.aligned.m16n8k16.row.col.f32.bf16.bf16.f32 "
                 "{%0,%1,%2,%3}, {%4,%5,%6,%7}, {%8,%9}, {%0,%1,%2,%3};"
                 : "+f"(d[0]), "+f"(d[1]), "+f"(d[2]), "+f"(d[3])
                 : "r"(a[0]), "r"(a[1]), "r"(a[2]), "r"(a[3]), "r"(b[0]), "r"(b[1]));
}
__device__ __forceinline__ void mma_fp16(float* d, const uint32_t* a, const uint32_t* b) {
    asm volatile("mma.sync.aligned.m16n8k16.row.col.f32.f16.f16.f32 "
                 "{%0,%1,%2,%3}, {%4,%5,%6,%7}, {%8,%9}, {%0,%1,%2,%3};"
                 : "+f"(d[0]), "+f"(d[1]), "+f"(d[2]), "+f"(d[3])
                 : "r"(a[0]), "r"(a[1]), "r"(a[2]), "r"(a[3]), "r"(b[0]), "r"(b[1]));
}
__device__ __forceinline__ void cpa16(uint32_t s, const void* g) {
    asm volatile("cp.async.cg.shared.global [%0], [%1], 16;" :: "r"(s), "l"(g) : "memory");
}
#define CP_COMMIT() asm volatile("cp.async.commit_group;" ::: "memory")
template <int N>
__device__ __forceinline__ void cp_wait() {
    asm volatile("cp.async.wait_group %0;" :: "n"(N) : "memory");
}

// ===========================================================================
// Generic split-precision GEMM via mma.sync: C(m,n) = sum_k A(m,k)*B(n,k).
// MODE 0: bf16x3 (Ah,Al,Bh,Bl; 3 MMAs). MODE 1: fp16x2 (Ah,Al,Bh; 2 MMAs).
// 256 threads, warp grid 2(m)x4(n). Multi-stage cp.async pipeline.
// Persistent 1D grid over ntot tiles; decode xo/yo/z, z = b*nsl + sl.
// EPI 0: fp32*scale. EPI 1: bf16 hi/lo. EPI 2: fp16 single *scale.
// ===========================================================================
template <int BM, int BN, int EPI, int KB, int MODE>
__global__ void __launch_bounds__(256, 1)
gemm_sp(const ushort_t* __restrict__ Ah, const ushort_t* __restrict__ Al,
        const ushort_t* __restrict__ Bh, const ushort_t* __restrict__ Bl,
        float* __restrict__ Cf, ushort_t* __restrict__ Ch, ushort_t* __restrict__ Cl,
        int K, int lda, int ldb, int ldc,
        long bA, long slA, long bB, long slB, long bC, long slC, int nsl,
        float scale, int ntx, int nty, int ntot) {
    constexpr int WM = BM / 2, WN = BN / 4;
    constexpr int MT = WM / 16, NT = WN / 8, PB = WN / 16;
    constexpr int SEGS = KB / 8;
    constexpr int SSH  = (KB == 64) ? 3 : 2;
    constexpr int KS   = KB / 16;
    constexpr int AB   = BM * KB * 2;
    constexpr int BB   = BN * KB * 2;
    constexpr int SS   = (MODE == 0) ? (2 * AB + 2 * BB) : (2 * AB + BB);
    constexpr int NSTG = (4 * SS <= 196608) ? 4 : 3;

    extern __shared__ char dsm[];
    uint32_t sb = smem_u32(dsm);
    int tid = threadIdx.x, lane = tid & 31, wid = tid >> 5;
    int wm = wid & 1, wn = wid >> 1;
    const int nkt = K / KB;

    auto rowoff = [](int r) -> uint32_t {
        return (KB == 32) ? (uint32_t)((r >> 1) * 128 + (r & 1) * 64)
                          : (uint32_t)(r * 128);
    };

#pragma unroll 1
    for (int t = blockIdx.x; t < ntot; t += gridDim.x) {
        int xo = t % ntx;
        int rest = t / ntx;
        int yo = rest % nty;
        int z = rest / nty;
        int b = z / nsl, sl = z - b * nsl;
        int m0 = yo * BM, n0 = xo * BN;
        const ushort_t* pAh = Ah + b * bA + sl * slA + (size_t)m0 * lda;
        const ushort_t* pAl = Al + b * bA + sl * slA + (size_t)m0 * lda;
        const ushort_t* pBh = Bh + b * bB + sl * slB + (size_t)n0 * ldb;
        const ushort_t* pBl = (MODE == 0) ? (Bl + b * bB + sl * slB + (size_t)n0 * ldb) : nullptr;

        float acc[MT][NT][4];
#pragma unroll
        for (int i = 0; i < MT; i++)
#pragma unroll
            for (int j = 0; j < NT; j++)
#pragma unroll
                for (int q = 0; q < 4; q++) acc[i][j][q] = 0.f;

        auto load_stage = [&](int stg, int kt, bool pred) {
            if (pred) {
                uint32_t s0 = sb + stg * SS;
                int ke = kt * KB;
#pragma unroll
                for (int c = tid; c < BM * SEGS; c += 256) {
                    int r = c >> SSH, sg = c & (SEGS - 1);
                    uint32_t o = SWZ(rowoff(r) + sg * 16);
                    cpa16(s0 + o,      pAh + (size_t)r * lda + ke + sg * 8);
                    cpa16(s0 + AB + o, pAl + (size_t)r * lda + ke + sg * 8);
                }
#pragma unroll
                for (int c = tid; c < BN * SEGS; c += 256) {
                    int r = c >> SSH, sg = c & (SEGS - 1);
                    uint32_t o = SWZ(rowoff(r) + sg * 16);
                    cpa16(s0 + 2 * AB + o, pBh + (size_t)r * ldb + ke + sg * 8);
                    if (MODE == 0)
                        cpa16(s0 + 2 * AB + BB + o, pBl + (size_t)r * ldb + ke + sg * 8);
                }
            }
            CP_COMMIT();
        };

#pragma unroll
        for (int s = 0; s < NSTG - 1; s++) load_stage(s, s, s < nkt);

#pragma unroll 1
        for (int kt = 0; kt < nkt; kt++) {
            cp_wait<NSTG - 2>();
            __syncthreads();
            load_stage((kt + NSTG - 1) % NSTG, kt + NSTG - 1, kt + NSTG - 1 < nkt);

            uint32_t stb = sb + (kt % NSTG) * SS;
#pragma unroll
            for (int ks = 0; ks < KS; ks++) {
                uint32_t ah[MT][4], al[MT][4], bh[PB][4], bl[PB][4];
                int ar  = wm * WM + (lane & 15);
                int akk = ks * 16 + (lane >> 4) * 8;
#pragma unroll
                for (int mt = 0; mt < MT; mt++) {
                    int r = ar + mt * 16;
                    uint32_t o = SWZ(rowoff(r) + akk * 2);
                    ldsm4(ah[mt], stb + o);
                    ldsm4(al[mt], stb + AB + o);
                }
                int bn  = wn * WN + (lane & 7) + ((lane >> 4) & 1) * 8;
                int bkk = ks * 16 + ((lane >> 3) & 1) * 8;
#pragma unroll
                for (int p = 0; p < PB; p++) {
                    int r = bn + p * 16;
                    uint32_t o = SWZ(rowoff(r) + bkk * 2);
                    ldsm4(bh[p], stb + 2 * AB + o);
                    if (MODE == 0) ldsm4(bl[p], stb + 2 * AB + BB + o);
                }
#pragma unroll
                for (int mt = 0; mt < MT; mt++)
#pragma unroll
                    for (int nt = 0; nt < NT; nt++) {
                        const uint32_t* fh = &bh[nt >> 1][(nt & 1) * 2];
                        if (MODE == 0) {
                            const uint32_t* fl = &bl[nt >> 1][(nt & 1) * 2];
                            mma_bf16(acc[mt][nt], ah[mt], fh);
                            mma_bf16(acc[mt][nt], al[mt], fh);
                            mma_bf16(acc[mt][nt], ah[mt], fl);
                        } else {
                            mma_fp16(acc[mt][nt], ah[mt], fh);
                            mma_fp16(acc[mt][nt], al[mt], fh);
                        }
                    }
            }
        }

        long offC = b * bC + sl * slC;
        int r0 = m0 + wm * WM + (lane >> 2);
        int c0 = n0 + wn * WN + (lane & 3) * 2;
        if (EPI == 0) {
            float* Co = Cf + offC;
#pragma unroll
            for (int mt = 0; mt < MT; mt++)
#pragma unroll
                for (int nt = 0; nt < NT; nt++) {
                    int r = r0 + mt * 16, c = c0 + nt * 8;
                    *(float2*)&Co[(size_t)r * ldc + c] =
                        make_float2(acc[mt][nt][0] * scale, acc[mt][nt][1] * scale);
                    *(float2*)&Co[(size_t)(r + 8) * ldc + c] =
                        make_float2(acc[mt][nt][2] * scale, acc[mt][nt][3] * scale);
                }
        } else if (EPI == 1) {
            ushort_t* Hh = Ch + offC;
            ushort_t* Hl = Cl + offC;
#pragma unroll
            for (int mt = 0; mt < MT; mt++)
#pragma unroll
                for (int nt = 0; nt < NT; nt++)
#pragma unroll
                    for (int hf = 0; hf < 2; hf++) {
                        int r = r0 + mt * 16 + hf * 8, c = c0 + nt * 8;
                        float v0 = acc[mt][nt][hf * 2], v1 = acc[mt][nt][hf * 2 + 1];
                        ushort_t h0 = f2bf(v0), h1 = f2bf(v1);
                        *(ushort2*)&Hh[(size_t)r * ldc + c] = make_ushort2(h0, h1);
                        *(ushort2*)&Hl[(size_t)r * ldc + c] =
                            make_ushort2(f2bf(v0 - bfhi(h0)), f2bf(v1 - bfhi(h1)));
                    }
        } else {   // EPI == 2: fp16 single, scaled
            ushort_t* Hh = Ch + offC;
#pragma unroll
            for (int mt = 0; mt < MT; mt++)
#pragma unroll
                for (int nt = 0; nt < NT; nt++)
#pragma unroll
                    for (int hf = 0; hf < 2; hf++) {
                        int r = r0 + mt * 16 + hf * 8, c = c0 + nt * 8;
                        *(ushort2*)&Hh[(size_t)r * ldc + c] =
                            make_ushort2(f2h(acc[mt][nt][hf * 2] * scale),
                                         f2h(acc[mt][nt][hf * 2 + 1] * scale));
                    }
        }
        __syncthreads();   // protect smem before next tile's prologue
    }
}

// ===========================================================================
// Fused input pack: x -> fp16 hi/lo (row-major + transposed); weights -> bf16
// ===========================================================================
__global__ void pack_all(const float* __restrict__ x, const float* __restrict__ Wq,
                         const float* __restrict__ Wk, const float* __restrict__ Wv,
                         const float* __restrict__ Wo) {
    __shared__ float s[32][33];
    int blk = blockIdx.x, tid = threadIdx.x;
    if (blk < 4096) {                      // x: transpose + row-major fp16 split
        int bx = blk & 127, by = (blk >> 7) & 15, b = blk >> 11;
        int r0 = bx * 32, c0 = by * 32;
        int tx = tid & 31, ty = tid >> 5;
        const float* xb = x + (size_t)b * bX;
#pragma unroll
        for (int q = 0; q < 4; q++) {
            int r = r0 + ty + 8 * q;
            float v = xb[(size_t)r * DIN + c0 + tx];
            s[ty + 8 * q][tx] = v;
            ushort_t h = f2h(v);
            size_t o = (size_t)b * bX + (size_t)r * DIN + c0 + tx;
            g_xh[o] = h;
            g_xl[o] = f2h(v - h2f(h));
        }
        __syncthreads();
#pragma unroll
        for (int q = 0; q < 4; q++) {
            int cd = ty + 8 * q;
            float v = s[tx][cd];
            ushort_t h = f2h(v);
            size_t o = ((size_t)b * DIN + c0 + cd) * LSEQ + r0 + tx;
            g_xTh[o] = h;
            g_xTl[o] = f2h(v - h2f(h));
        }
    } else if (blk < 5120) {               // Wkb[c][m] = Wk[h][m][k]
        int i = (blk - 4096) * 256 + tid;
        int c = i >> 9, m = i & 511, h = c >> 6, kd = c & 63;
        float v = Wk[h * 32768 + m * 64 + kd];
        ushort_t hh = f2bf(v);
        g_Wkbh[i] = hh; g_Wkbl[i] = f2bf(v - bfhi(hh));
    } else if (blk < 6144) {               // Wob[o][hv] = Wo[hv][o]
        int i = (blk - 5120) * 256 + tid;
        int o = i >> 9, hv = i & 511;
        float v = Wo[hv * 512 + o];
        ushort_t hh = f2bf(v);
        g_Wobh[i] = hh; g_Wobl[i] = f2bf(v - bfhi(hh));
    } else if (blk < 7168) {               // WvT[hv][n] = Wv[h][n][v]
        int i = (blk - 6144) * 256 + tid;
        int row = i >> 9, n = i & 511, h = row >> 6, vv = row & 63;
        float v = Wv[h * 32768 + n * 64 + vv];
        ushort_t hh = f2bf(v);
        g_WvTh[i] = hh; g_WvTl[i] = f2bf(v - bfhi(hh));
    } else {                               // Wqb straight split
        int i = (blk - 7168) * 256 + tid;
        float v = Wq[i];
        ushort_t hh = f2bf(v);
        g_Wqbh[i] = hh; g_Wqbl[i] = f2bf(v - bfhi(hh));
    }
}

// ===========================================================================
// reduce_4: sum 4 fp32 partials per batch -> bf16 hi/lo (for G)
// ===========================================================================
__global__ void reduce_4(const float* __restrict__ src,
                         ushort_t* __restrict__ oh, ushort_t* __restrict__ ol) {
    int i = blockIdx.x * 256 + threadIdx.x;
    int b = i >> 16, e = i & 65535;
    const float4* p = (const float4*)src;
    float4 v = p[(size_t)(b * 4) * 65536 + e];
#pragma unroll
    for (int q = 1; q < 4; q++) {
        float4 t = p[(size_t)(b * 4 + q) * 65536 + e];
        v.x += t.x; v.y += t.y; v.z += t.z; v.w += t.w;
    }
    ushort_t h0 = f2bf(v.x), h1 = f2bf(v.y), h2 = f2bf(v.z), h3 = f2bf(v.w);
    size_t o = (size_t)b * 65536 + e;
    ((ushort4*)oh)[o] = make_ushort4(h0, h1, h2, h3);
    ((ushort4*)ol)[o] = make_ushort4(f2bf(v.x - bfhi(h0)), f2bf(v.y - bfhi(h1)),
                                     f2bf(v.z - bfhi(h2)), f2bf(v.w - bfhi(h3)));
}

// ===========================================================================
extern "C" void kernel_launch(void* const* d_in, const int* in_sizes, int n_in,
                              void* d_out, int out_size) {
    const float* x  = (const float*)d_in[0];
    const float* Wq = (const float*)d_in[1];
    const float* Wk = (const float*)d_in[2];
    const float* Wv = (const float*)d_in[3];
    const float* Wo = (const float*)d_in[4];
    float* out = (float*)d_out;

    const float SC_DOWN = 5.9604644775390625e-8f;   // 2^-24
    const float SC_UP   = 16777216.0f;              // 2^24

    cudaFuncSetAttribute(gemm_sp<128,128,0,32,1>, cudaFuncAttributeMaxDynamicSharedMemorySize, 98304);
    cudaFuncSetAttribute(gemm_sp<64,64,1,64,0>,   cudaFuncAttributeMaxDynamicSharedMemorySize, 131072);
    cudaFuncSetAttribute(gemm_sp<64,64,2,64,0>,   cudaFuncAttributeMaxDynamicSharedMemorySize, 131072);
    cudaFuncSetAttribute(gemm_sp<128,64,1,64,0>,  cudaFuncAttributeMaxDynamicSharedMemorySize, 196608);

    ushort_t *xh,*xl,*xTh,*xTl,*Gh,*Gl,*PTh,*PTl,*RTh,*RTl,*Uh,*Ul,*CTh;
    ushort_t *Wkbh,*Wkbl,*Wobh,*Wobl,*WvTh,*WvTl,*Wqbh,*Wqbl;
    float *Gp;
    cudaGetSymbolAddress((void**)&xh,  g_xh);  cudaGetSymbolAddress((void**)&xl,  g_xl);
    cudaGetSymbolAddress((void**)&xTh, g_xTh); cudaGetSymbolAddress((void**)&xTl, g_xTl);
    cudaGetSymbolAddress((void**)&Gh,  g_Gh);  cudaGetSymbolAddress((void**)&Gl,  g_Gl);
    cudaGetSymbolAddress((void**)&PTh, g_PTh); cudaGetSymbolAddress((void**)&PTl, g_PTl);
    cudaGetSymbolAddress((void**)&RTh, g_RTh); cudaGetSymbolAddress((void**)&RTl, g_RTl);
    cudaGetSymbolAddress((void**)&Uh,  g_Uh);  cudaGetSymbolAddress((void**)&Ul,  g_Ul);
    cudaGetSymbolAddress((void**)&CTh, g_CTh);
    cudaGetSymbolAddress((void**)&Wkbh,g_Wkbh);cudaGetSymbolAddress((void**)&Wkbl,g_Wkbl);
    cudaGetSymbolAddress((void**)&Wobh,g_Wobh);cudaGetSymbolAddress((void**)&Wobl,g_Wobl);
    cudaGetSymbolAddress((void**)&WvTh,g_WvTh);cudaGetSymbolAddress((void**)&WvTl,g_WvTl);
    cudaGetSymbolAddress((void**)&Wqbh,g_Wqbh);cudaGetSymbolAddress((void**)&Wqbl,g_Wqbl);
    cudaGetSymbolAddress((void**)&Gp,  g_Gp);

    pack_all<<<8192, 256>>>(x, Wq, Wk, Wv, Wo);

    // G[n][m] = sum_l xT[n][l] xT[m][l]; fp16x2, split-K 4 (128 tiles)
    gemm_sp<128,128,0,32,1><<<128, 256, 98304>>>(
        xTh, xTl, xTh, nullptr, Gp, nullptr, nullptr,
        1024, LSEQ, LSEQ, 512,
        (long)bX, 1024, (long)bX, 1024, (long)(4*bS), (long)bS, 4,
        1.0f, 4, 4, 128);
    reduce_4<<<512, 256>>>(Gp, Gh, Gl);

    // PT[c][n] = sum_m Wkb[c][m] G[n][m]; bf16x3, 64x64, KB=64 (128 tiles)
    gemm_sp<64,64,1,64,0><<<128, 256, 131072>>>(
        Wkbh, Wkbl, Gh, Gl, nullptr, PTh, PTl,
        512, 512, 512, 512,
        0, 0, (long)bS, 0, (long)bS, 0, 1,
        1.0f, 8, 8, 128);

    // RT[v][k](b,h) = sum_n WvT[hv][n] PT[hk][n]; batched (b,h) (16 tiles)
    gemm_sp<64,64,1,64,0><<<16, 256, 131072>>>(
        WvTh, WvTl, PTh, PTl, nullptr, RTh, RTl,
        512, 512, 512, 64,
        0, 32768, (long)bS, 32768, (long)(NH*4096), 4096, NH,
        1.0f, 1, 1, 16);

    // U[j][hv](b) = sum_k Wqb[hj][k] RT[v][k]; batched (b,h) (64 tiles)
    gemm_sp<128,64,1,64,0><<<64, 256, 196608>>>(
        Wqbh, Wqbl, RTh, RTl, nullptr, Uh, Ul,
        64, 64, 64, 512,
        0, 32768, (long)(NH*4096), 4096, (long)bS, 64, NH,
        1.0f, 1, 4, 64);

    // CT[o][j](b) = sum_hv Wob[o][hv] U[j][hv]; bf16x3 -> fp16 scaled (128 tiles)
    gemm_sp<64,64,2,64,0><<<128, 256, 131072>>>(
        Wobh, Wobl, Uh, Ul, nullptr, CTh, nullptr,
        512, 512, 512, 512,
        0, 0, (long)bS, 0, (long)bS, 0, 1,
        SC_DOWN, 8, 8, 128);

    // out[l][o] = sum_j x[l][j] CT[o][j]; fp16x2, rescale 2^24 (256 tiles)
    gemm_sp<128,128,0,32,1><<<148, 256, 98304>>>(
        xh, xl, CTh, nullptr, out, nullptr, nullptr,
        512, 512, 512, 512,
        (long)bX, 0, (long)bS, 0, (long)bX, 0, 1,
        SC_UP, 4, 32, 256);
}